// round 9
// baseline (speedup 1.0000x reference)
#include <cuda_runtime.h>

// All-pairs N-body gravity — hybrid rsqrt to break the fma-pipe floor.
// Measured invariant: every variant pins at ~64K cyc = 18 fma-pipe cyc per
// 32-pair group (fma rt_SMSP=2). Fix: compute s = m*r2^-1.5 in log domain,
//   s = exp2(fma(-1.5, lg2(r2), lg2_m))           [2 MUFU + 1 FFMA-imm(rt1)]
// for 3 of 4 j's, classic MUFU.RSQ + muls for the 4th — balancing fma pipe
// (14.25 cyc/grp) against MUFU (14 cyc/grp). lg2(m_j) precomputed at staging;
// shared w holds lg2(m) for log-path t's and raw m for rsq-path t's.

#define BLOCK  128
#define IPT    4
#define JCHUNK 64
#define EPS2   0.0001f   // SOFTENING^2

__device__ __forceinline__ float rsq_mufu(float x) {
    float r; asm("rsqrt.approx.f32 %0, %1;" : "=f"(r) : "f"(x)); return r;
}
__device__ __forceinline__ float lg2_mufu(float x) {
    float r; asm("lg2.approx.f32 %0, %1;" : "=f"(r) : "f"(x)); return r;
}
__device__ __forceinline__ float ex2_mufu(float x) {
    float r; asm("ex2.approx.f32 %0, %1;" : "=f"(r) : "f"(x)); return r;
}

__global__ void zero_out_kernel(float* __restrict__ out, int n) {
    int i = blockIdx.x * blockDim.x + threadIdx.x;
    if (i < n) out[i] = 0.0f;
}

__global__ __launch_bounds__(BLOCK)
void nbody_forces_kernel(const float* __restrict__ pos,
                         const float* __restrict__ mass,
                         float* __restrict__ out) {
    __shared__ float4 sj[JCHUNK];   // {x, y, z, (t%4==3 ? m : lg2(m))}

    const int tid   = threadIdx.x;
    const int ibase = blockIdx.x * (BLOCK * IPT) + tid;
    const int jbase = blockIdx.y * JCHUNK;

    if (tid < JCHUNK) {
        int j = jbase + tid;
        float m = mass[j];
        float w = ((tid & 3) == 3) ? m : lg2_mufu(m);
        sj[tid] = make_float4(pos[3 * j + 0], pos[3 * j + 1], pos[3 * j + 2], w);
    }
    __syncthreads();

    float xi[IPT], yi[IPT], zi[IPT];
    float ax[IPT], ay[IPT], az[IPT];
#pragma unroll
    for (int k = 0; k < IPT; ++k) {
        int i = ibase + k * BLOCK;
        xi[k] = pos[3 * i + 0];
        yi[k] = pos[3 * i + 1];
        zi[k] = pos[3 * i + 2];
        ax[k] = 0.0f; ay[k] = 0.0f; az[k] = 0.0f;
    }

#pragma unroll 4
    for (int t = 0; t < JCHUNK; ++t) {
        const float4 p = sj[t];        // LDS.128 broadcast feeds IPT pairs
        const bool rsq_path = ((t & 3) == 3);   // compile-time in unroll
#pragma unroll
        for (int k = 0; k < IPT; ++k) {
            float dx = p.x - xi[k];
            float dy = p.y - yi[k];
            float dz = p.z - zi[k];
            float r2 = fmaf(dx, dx, fmaf(dy, dy, fmaf(dz, dz, EPS2)));
            float s;
            if (rsq_path) {
                float inv = rsq_mufu(r2);                 // 1 MUFU
                s = (p.w * inv) * (inv * inv);            // 3 FMUL (fma pipe)
            } else {
                // s = m * r2^-1.5 = exp2(-1.5*lg2(r2) + lg2(m))
                float L = lg2_mufu(r2);                   // MUFU.LG2
                s = ex2_mufu(fmaf(-1.5f, L, p.w));        // FFMA-imm + MUFU.EX2
            }
            ax[k] = fmaf(s, dx, ax[k]);
            ay[k] = fmaf(s, dy, ay[k]);
            az[k] = fmaf(s, dz, az[k]);
        }
    }

#pragma unroll
    for (int k = 0; k < IPT; ++k) {
        int i = ibase + k * BLOCK;
        atomicAdd(&out[3 * i + 0], ax[k]);
        atomicAdd(&out[3 * i + 1], ay[k]);
        atomicAdd(&out[3 * i + 2], az[k]);
    }
}

extern "C" void kernel_launch(void* const* d_in, const int* in_sizes, int n_in,
                              void* d_out, int out_size) {
    const float* pos  = (const float*)d_in[0];   // [N,3] float32
    const float* mass = (const float*)d_in[1];   // [N]   float32
    float* out = (float*)d_out;                  // [N,3] float32

    const int n = in_sizes[0] / 3;               // 8192

    zero_out_kernel<<<(out_size + 255) / 256, 256>>>(out, out_size);

    dim3 grid(n / (BLOCK * IPT), n / JCHUNK);    // 16 x 128 = 2048 CTAs
    nbody_forces_kernel<<<grid, BLOCK>>>(pos, mass, out);
}